// round 6
// baseline (speedup 1.0000x reference)
#include <cuda_runtime.h>
#include <cuda_bf16.h>

// One CTA per 64x64 image, 256 threads.
// Image staged into ZERO-PADDED smem (66 rows x 72 stride, image at [r+1][c+4]):
// all window reads are unguarded LDS (1 vec + 2 scalar per row), no shuffles/SELs.
// Thread t: col quad q=t&15 (cols 4q..4q+3), rows 4*(t>>4)..+3, vertical sliding window.
// |gx|+|gy| == max(|conv(S)|, |conv(D)|), S=wr+wr^T, D=wr-wr^T.
// Weight prep done once by warp 0 -> smem coeffs.

#define FULL 0xffffffffu
#define NUM_IMG 2048
#define SROW 72

__global__ __launch_bounds__(256)
void sobel_norm_kernel(const float* __restrict__ in,
                       const float* __restrict__ w,
                       const float* __restrict__ wf,
                       const float* __restrict__ scale_p,
                       float* __restrict__ out) {
    __shared__ float simg[66 * SROW];   // ~19 KB padded image
    __shared__ float scoef[12];         // s00,s11,s22,s01,s02,s12,d01,d02,d12,isc
    __shared__ float smin[8];
    __shared__ float smax[8];

    const int img = blockIdx.x;
    const int tid = threadIdx.x;
    const int q   = tid & 15;        // col quad 0..15
    const int r0  = (tid >> 4) << 2; // first output row (0..60)

    // --- Stage image into padded smem (coalesced float4 in, aligned float4 STS) ---
    const float4* __restrict__ in4 = reinterpret_cast<const float4*>(in + (size_t)img * 4096);
#pragma unroll
    for (int i = 0; i < 4; i++) {
        const int e  = tid + i * 256;     // float4 index 0..1023
        const int r  = e >> 4;            // image row
        const int cq = e & 15;            // col quad
        *reinterpret_cast<float4*>(&simg[(r + 1) * SROW + 4 + (cq << 2)]) = in4[e];
    }
    // zero borders: rows 0 and 65 fully; cols 3 and 68 for rows 1..64
    if (tid < 72) { simg[tid] = 0.f; simg[65 * SROW + tid] = 0.f; }
    if (tid < 64) { simg[(tid + 1) * SROW + 3] = 0.f; simg[(tid + 1) * SROW + 68] = 0.f; }

    // --- Weight prep: warp 0 only, broadcast via shfl, thread 0 writes coeffs ---
    if (tid < 32) {
        float wv = 0.f;
        if (tid < 9) {
            const float f = fminf(fmaxf(__ldg(wf), 1.0f), 255.0f);
            wv = fminf(fmaxf(__ldg(w + tid), -1.0f), 1.0f) * f;
        }
        const float w0 = __shfl_sync(FULL, wv, 0);
        const float w1 = __shfl_sync(FULL, wv, 1);
        const float w2 = __shfl_sync(FULL, wv, 2);
        const float w3 = __shfl_sync(FULL, wv, 3);
        const float w4 = __shfl_sync(FULL, wv, 4);
        const float w5 = __shfl_sync(FULL, wv, 5);
        const float w6 = __shfl_sync(FULL, wv, 6);
        const float w7 = __shfl_sync(FULL, wv, 7);
        const float w8 = __shfl_sync(FULL, wv, 8);
        if (tid == 0) {
            scoef[0] = w0 + w0;   // s00
            scoef[1] = w4 + w4;   // s11
            scoef[2] = w8 + w8;   // s22
            scoef[3] = w1 + w3;   // s01
            scoef[4] = w2 + w6;   // s02
            scoef[5] = w5 + w7;   // s12
            scoef[6] = w1 - w3;   // d01
            scoef[7] = w2 - w6;   // d02
            scoef[8] = w5 - w7;   // d12
            scoef[9] = 1.0f / __ldg(scale_p);
        }
    }
    __syncthreads();

    const float s00 = scoef[0], s11 = scoef[1], s22 = scoef[2];
    const float s01 = scoef[3], s02 = scoef[4], s12 = scoef[5];
    const float d01 = scoef[6], d02 = scoef[7], d12 = scoef[8];
    const float isc = scoef[9];

    // --- Conv with vertical sliding window; all reads unguarded ---
    const float* __restrict__ sbase = simg + 4 + (q << 2);
    float W[3][6];

    auto ldrow = [&](int sr, float* V) {   // sr = smem row index (image row + 1)
        const float* rp = sbase + sr * SROW;
        const float4 m = *reinterpret_cast<const float4*>(rp);
        V[0] = rp[-1];
        V[1] = m.x; V[2] = m.y; V[3] = m.z; V[4] = m.w;
        V[5] = rp[4];
    };

    ldrow(r0,     W[0]);   // image row r0-1
    ldrow(r0 + 1, W[1]);   // image row r0

    float g[16];
    float gmn = 3.4e38f;
    float gmx = 0.0f;   // g >= 0

#pragma unroll
    for (int i = 0; i < 4; i++) {
        ldrow(r0 + 2 + i, W[(i + 2) % 3]);
        const float* a = W[i % 3];           // top
        const float* b = W[(i + 1) % 3];     // mid
        const float* c = W[(i + 2) % 3];     // bot
#pragma unroll
        for (int p = 0; p < 4; p++) {
            const float a0 = a[p], a1 = a[p + 1], a2 = a[p + 2];
            const float b0 = b[p], b1 = b[p + 1], b2 = b[p + 2];
            const float c1 = c[p], c2 = c[p + 1], c3 = c[p + 2];
            // S = conv(wr + wr^T) = gx + gy
            float S = s00 * a0;
            S = fmaf(s11, b1, S);
            S = fmaf(s22, c3, S);
            S = fmaf(s01, a1 + b0, S);
            S = fmaf(s02, a2 + c1, S);
            S = fmaf(s12, b2 + c2, S);
            // D = conv(wr - wr^T) = gx - gy  (diagonal vanishes)
            float D = d01 * (a1 - b0);
            D = fmaf(d02, a2 - c1, D);
            D = fmaf(d12, b2 - c2, D);
            // |gx| + |gy| = max(|S|, |D|)
            const float gv = fmaxf(fabsf(S), fabsf(D));
            g[i * 4 + p] = gv;
            gmn = fminf(gmn, gv);
            gmx = fmaxf(gmx, gv);
        }
    }

    // --- block min/max reduction ---
#pragma unroll
    for (int o = 16; o; o >>= 1) {
        gmn = fminf(gmn, __shfl_xor_sync(FULL, gmn, o));
        gmx = fmaxf(gmx, __shfl_xor_sync(FULL, gmx, o));
    }
    if ((tid & 31) == 0) { smin[tid >> 5] = gmn; smax[tid >> 5] = gmx; }
    __syncthreads();
    gmn = smin[0]; gmx = smax[0];
#pragma unroll
    for (int i = 1; i < 8; i++) {
        gmn = fminf(gmn, smin[i]);
        gmx = fmaxf(gmx, smax[i]);
    }

    const float mul = 255.0f / fmaxf(gmx - gmn, 1.0f);
    const float nb  = -gmn * mul;

    // --- normalize + floor + scale; float4 stores ---
    float* __restrict__ op = out + (size_t)img * 4096 + (r0 << 6) + (q << 2);
#pragma unroll
    for (int i = 0; i < 4; i++) {
        float4 o4;
        o4.x = floorf(fmaf(g[i * 4 + 0], mul, nb)) * isc;
        o4.y = floorf(fmaf(g[i * 4 + 1], mul, nb)) * isc;
        o4.z = floorf(fmaf(g[i * 4 + 2], mul, nb)) * isc;
        o4.w = floorf(fmaf(g[i * 4 + 3], mul, nb)) * isc;
        *reinterpret_cast<float4*>(op + (i << 6)) = o4;
    }
}

extern "C" void kernel_launch(void* const* d_in, const int* in_sizes, int n_in,
                              void* d_out, int out_size) {
    const float* in      = (const float*)d_in[0];  // (2048,1,64,64) fp32
    const float* w       = (const float*)d_in[1];  // (1,9) fp32
    const float* wf      = (const float*)d_in[2];  // (1,) fp32
    const float* scale_p = (const float*)d_in[3];  // (1,1) fp32
    float* out = (float*)d_out;                    // (1,2048,1,64,64) fp32
    (void)in_sizes; (void)n_in; (void)out_size;

    sobel_norm_kernel<<<NUM_IMG, 256>>>(in, w, wf, scale_p, out);
}

// round 8
// speedup vs baseline: 1.0105x; 1.0105x over previous
#include <cuda_runtime.h>
#include <cuda_bf16.h>

// Two kernels: coeff_kernel (1 thread) precomputes S/D conv coefficients + 1/scale
// into __device__ globals; sobel kernel (1 CTA per 64x64 image, 256 threads).
// Thread t: col quad q=t&15 (cols 4q..4q+3), rows 4*(t>>4)..+3.
// Direct global reads (L2-resident): per row 1 LDG.128 + 2 predicated scalar LDG (halo).
// |gx|+|gy| == max(|conv(S)|, |conv(D)|), S=wr+wr^T, D=wr-wr^T.
// Warp min/max via redux.sync.u32 on float bits (valid: g >= 0 -> monotone bit order).

#define FULL 0xffffffffu
#define NUM_IMG 2048

__device__ float g_coef[10];

__global__ void coeff_kernel(const float* __restrict__ w,
                             const float* __restrict__ wf,
                             const float* __restrict__ scale_p) {
    const float f = fminf(fmaxf(wf[0], 1.0f), 255.0f);
    float wr[9];
#pragma unroll
    for (int i = 0; i < 9; i++)
        wr[i] = fminf(fmaxf(w[i], -1.0f), 1.0f) * f;
    g_coef[0] = wr[0] + wr[0];   // s00
    g_coef[1] = wr[4] + wr[4];   // s11
    g_coef[2] = wr[8] + wr[8];   // s22
    g_coef[3] = wr[1] + wr[3];   // s01
    g_coef[4] = wr[2] + wr[6];   // s02
    g_coef[5] = wr[5] + wr[7];   // s12
    g_coef[6] = wr[1] - wr[3];   // d01
    g_coef[7] = wr[2] - wr[6];   // d02
    g_coef[8] = wr[5] - wr[7];   // d12
    g_coef[9] = 1.0f / scale_p[0];
}

__global__ __launch_bounds__(256)
void sobel_norm_kernel(const float* __restrict__ in,
                       float* __restrict__ out) {
    __shared__ float swarp[16];   // [w*2]=min, [w*2+1]=max

    const int img = blockIdx.x;
    const int tid = threadIdx.x;
    const int q   = tid & 15;        // col quad 0..15
    const int r0  = (tid >> 4) << 2; // first output row (0..60)
    const int c0  = q << 2;

    const float s00 = __ldg(&g_coef[0]), s11 = __ldg(&g_coef[1]), s22 = __ldg(&g_coef[2]);
    const float s01 = __ldg(&g_coef[3]), s02 = __ldg(&g_coef[4]), s12 = __ldg(&g_coef[5]);
    const float d01 = __ldg(&g_coef[6]), d02 = __ldg(&g_coef[7]), d12 = __ldg(&g_coef[8]);
    const float isc = __ldg(&g_coef[9]);

    const bool pl = (q != 0);
    const bool pr = (q != 15);

    const float* __restrict__ base = in + (size_t)img * 4096 + (r0 << 6) + c0;

    // Sliding 3-row window; each row is 6 floats: cols c0-1 .. c0+4.
    float W[3][6];

    auto ldrow_in = [&](int koff, float* V) {   // row known in-bounds
        const float4 m = *reinterpret_cast<const float4*>(base + koff);
        V[1] = m.x; V[2] = m.y; V[3] = m.z; V[4] = m.w;
        V[0] = pl ? base[koff - 1] : 0.0f;
        V[5] = pr ? base[koff + 4] : 0.0f;
    };

    // top halo row (image row r0-1)
    if (r0 != 0) ldrow_in(-64, W[0]);
    else { W[0][0]=0.f; W[0][1]=0.f; W[0][2]=0.f; W[0][3]=0.f; W[0][4]=0.f; W[0][5]=0.f; }
    ldrow_in(0, W[1]);

    float g[16];
    float gmn = 3.4e38f;
    float gmx = 0.0f;   // g >= 0

#pragma unroll
    for (int i = 0; i < 4; i++) {
        float* nxt = W[(i + 2) % 3];
        if (i < 3) ldrow_in((i + 1) << 6, nxt);
        else if (r0 != 60) ldrow_in(4 << 6, nxt);
        else { nxt[0]=0.f; nxt[1]=0.f; nxt[2]=0.f; nxt[3]=0.f; nxt[4]=0.f; nxt[5]=0.f; }

        const float* a = W[i % 3];           // top
        const float* b = W[(i + 1) % 3];     // mid
        const float* c = W[(i + 2) % 3];     // bot
#pragma unroll
        for (int p = 0; p < 4; p++) {
            const float a0 = a[p], a1 = a[p + 1], a2 = a[p + 2];
            const float b0 = b[p], b1 = b[p + 1], b2 = b[p + 2];
            const float c1 = c[p], c2 = c[p + 1], c3 = c[p + 2];
            // S = conv(wr + wr^T) = gx + gy
            float S = s00 * a0;
            S = fmaf(s11, b1, S);
            S = fmaf(s22, c3, S);
            S = fmaf(s01, a1 + b0, S);
            S = fmaf(s02, a2 + c1, S);
            S = fmaf(s12, b2 + c2, S);
            // D = conv(wr - wr^T) = gx - gy  (diagonal vanishes)
            float D = d01 * (a1 - b0);
            D = fmaf(d02, a2 - c1, D);
            D = fmaf(d12, b2 - c2, D);
            // |gx| + |gy| = max(|S|, |D|)
            const float gv = fmaxf(fabsf(S), fabsf(D));
            g[i * 4 + p] = gv;
            gmn = fminf(gmn, gv);
            gmx = fmaxf(gmx, gv);
        }
    }

    // --- warp reduction: integer redux on float bits (all g >= 0) ---
    unsigned wmn_u, wmx_u;
    asm("redux.sync.min.u32 %0, %1, 0xffffffff;" : "=r"(wmn_u) : "r"(__float_as_uint(gmn)));
    asm("redux.sync.max.u32 %0, %1, 0xffffffff;" : "=r"(wmx_u) : "r"(__float_as_uint(gmx)));
    if ((tid & 31) == 0) {
        swarp[((tid >> 5) << 1) + 0] = __uint_as_float(wmn_u);
        swarp[((tid >> 5) << 1) + 1] = __uint_as_float(wmx_u);
    }
    __syncthreads();

    // --- cross-warp combine: 4x LDS.128, mins in .x/.z, maxs in .y/.w ---
    const float4 p0 = *reinterpret_cast<const float4*>(&swarp[0]);
    const float4 p1 = *reinterpret_cast<const float4*>(&swarp[4]);
    const float4 p2 = *reinterpret_cast<const float4*>(&swarp[8]);
    const float4 p3 = *reinterpret_cast<const float4*>(&swarp[12]);
    gmn = fminf(fminf(fminf(p0.x, p0.z), fminf(p1.x, p1.z)),
                fminf(fminf(p2.x, p2.z), fminf(p3.x, p3.z)));
    gmx = fmaxf(fmaxf(fmaxf(p0.y, p0.w), fmaxf(p1.y, p1.w)),
                fmaxf(fmaxf(p2.y, p2.w), fmaxf(p3.y, p3.w)));

    const float mul = 255.0f / fmaxf(gmx - gmn, 1.0f);
    const float nb  = -gmn * mul;

    // --- normalize + floor (+scale); float4 stores ---
    float* __restrict__ op = out + (size_t)img * 4096 + (r0 << 6) + c0;
    if (isc == 1.0f) {
#pragma unroll
        for (int i = 0; i < 4; i++) {
            float4 o4;
            o4.x = floorf(fmaf(g[i * 4 + 0], mul, nb));
            o4.y = floorf(fmaf(g[i * 4 + 1], mul, nb));
            o4.z = floorf(fmaf(g[i * 4 + 2], mul, nb));
            o4.w = floorf(fmaf(g[i * 4 + 3], mul, nb));
            *reinterpret_cast<float4*>(op + (i << 6)) = o4;
        }
    } else {
#pragma unroll
        for (int i = 0; i < 4; i++) {
            float4 o4;
            o4.x = floorf(fmaf(g[i * 4 + 0], mul, nb)) * isc;
            o4.y = floorf(fmaf(g[i * 4 + 1], mul, nb)) * isc;
            o4.z = floorf(fmaf(g[i * 4 + 2], mul, nb)) * isc;
            o4.w = floorf(fmaf(g[i * 4 + 3], mul, nb)) * isc;
            *reinterpret_cast<float4*>(op + (i << 6)) = o4;
        }
    }
}

extern "C" void kernel_launch(void* const* d_in, const int* in_sizes, int n_in,
                              void* d_out, int out_size) {
    const float* in      = (const float*)d_in[0];  // (2048,1,64,64) fp32
    const float* w       = (const float*)d_in[1];  // (1,9) fp32
    const float* wf      = (const float*)d_in[2];  // (1,) fp32
    const float* scale_p = (const float*)d_in[3];  // (1,1) fp32
    float* out = (float*)d_out;                    // (1,2048,1,64,64) fp32
    (void)in_sizes; (void)n_in; (void)out_size;

    coeff_kernel<<<1, 1>>>(w, wf, scale_p);
    sobel_norm_kernel<<<NUM_IMG, 256>>>(in, out);
}

// round 9
// speedup vs baseline: 1.2829x; 1.2695x over previous
#include <cuda_runtime.h>
#include <cuda_bf16.h>

// coeff_kernel (1 thread) precomputes S/D conv coefficients + 1/scale into
// __device__ globals. sobel kernel: 1 CTA per 64x64 image, 256 threads.
// Thread t: col quad q=t&15 (cols 4q..4q+3), rows 4*(t>>4)..+3.
// Rows read as LDG.128 (L2-resident), halo via warp shuffle (R3-proven).
// Row loads software-pipelined ONE ITERATION ahead of their use.
// |gx|+|gy| == max(|conv(S)|, |conv(D)|), S=wr+wr^T, D=wr-wr^T.
// Warp min/max via redux.sync.u32 on float bits (valid: g >= 0).

#define FULL 0xffffffffu
#define NUM_IMG 2048

__device__ float g_coef[10];

__global__ void coeff_kernel(const float* __restrict__ w,
                             const float* __restrict__ wf,
                             const float* __restrict__ scale_p) {
    const float f = fminf(fmaxf(wf[0], 1.0f), 255.0f);
    float wr[9];
#pragma unroll
    for (int i = 0; i < 9; i++)
        wr[i] = fminf(fmaxf(w[i], -1.0f), 1.0f) * f;
    g_coef[0] = wr[0] + wr[0];   // s00
    g_coef[1] = wr[4] + wr[4];   // s11
    g_coef[2] = wr[8] + wr[8];   // s22
    g_coef[3] = wr[1] + wr[3];   // s01
    g_coef[4] = wr[2] + wr[6];   // s02
    g_coef[5] = wr[5] + wr[7];   // s12
    g_coef[6] = wr[1] - wr[3];   // d01
    g_coef[7] = wr[2] - wr[6];   // d02
    g_coef[8] = wr[5] - wr[7];   // d12
    g_coef[9] = 1.0f / scale_p[0];
}

__global__ __launch_bounds__(256)
void sobel_norm_kernel(const float* __restrict__ in,
                       float* __restrict__ out) {
    __shared__ float swarp[16];   // [w*2]=min, [w*2+1]=max

    const int img = blockIdx.x;
    const int tid = threadIdx.x;
    const int q   = tid & 15;        // col quad 0..15
    const int r0  = (tid >> 4) << 2; // first output row (0..60)
    const int c0  = q << 2;

    const float s00 = __ldg(&g_coef[0]), s11 = __ldg(&g_coef[1]), s22 = __ldg(&g_coef[2]);
    const float s01 = __ldg(&g_coef[3]), s02 = __ldg(&g_coef[4]), s12 = __ldg(&g_coef[5]);
    const float d01 = __ldg(&g_coef[6]), d02 = __ldg(&g_coef[7]), d12 = __ldg(&g_coef[8]);
    const float isc = __ldg(&g_coef[9]);

    const float* __restrict__ base = in + (size_t)img * 4096 + (r0 << 6) + c0;

    auto ldrow4 = [&](int koff, bool valid) -> float4 {
        float4 m = make_float4(0.f, 0.f, 0.f, 0.f);
        if (valid) m = *reinterpret_cast<const float4*>(base + koff);
        return m;
    };
    auto expand = [&](float4 m, float* V) {
        float lf = __shfl_up_sync(FULL, m.w, 1);
        float rg = __shfl_down_sync(FULL, m.x, 1);
        if (q == 0)  lf = 0.f;
        if (q == 15) rg = 0.f;
        V[0] = lf;
        V[1] = m.x; V[2] = m.y; V[3] = m.z; V[4] = m.w;
        V[5] = rg;
    };

    float g[16];
    float gmn = 3.4e38f;
    float gmx = 0.0f;   // g >= 0

    float W[3][6];

    auto conv4 = [&](const float* a, const float* b, const float* c, float* go) {
#pragma unroll
        for (int p = 0; p < 4; p++) {
            const float a0 = a[p], a1 = a[p + 1], a2 = a[p + 2];
            const float b0 = b[p], b1 = b[p + 1], b2 = b[p + 2];
            const float c1 = c[p], c2 = c[p + 1], c3 = c[p + 2];
            float S = s00 * a0;
            S = fmaf(s11, b1, S);
            S = fmaf(s22, c3, S);
            S = fmaf(s01, a1 + b0, S);
            S = fmaf(s02, a2 + c1, S);
            S = fmaf(s12, b2 + c2, S);
            float D = d01 * (a1 - b0);
            D = fmaf(d02, a2 - c1, D);
            D = fmaf(d12, b2 - c2, D);
            const float gv = fmaxf(fabsf(S), fabsf(D));
            go[p] = gv;
            gmn = fminf(gmn, gv);
            gmx = fmaxf(gmx, gv);
        }
    };

    // Preload first 3 rows (r0-1, r0, r0+1); expand first two.
    float4 mA = ldrow4(-64, r0 != 0);
    float4 mB = ldrow4(0,   true);
    float4 mC = ldrow4(64,  true);
    expand(mA, W[0]);
    expand(mB, W[1]);

    // Pipelined: LDG for row i+3 issued one full conv body before its expand.
    float4 mD = ldrow4(128, true);            // row r0+2
    expand(mC, W[2]);
    conv4(W[0], W[1], W[2], g + 0);

    mA = ldrow4(192, true);                   // row r0+3
    expand(mD, W[0]);
    conv4(W[1], W[2], W[0], g + 4);

    mB = ldrow4(256, r0 != 60);               // row r0+4 (guarded)
    expand(mA, W[1]);
    conv4(W[2], W[0], W[1], g + 8);

    expand(mB, W[2]);
    conv4(W[0], W[1], W[2], g + 12);

    // --- warp reduction: integer redux on float bits (all g >= 0) ---
    unsigned wmn_u, wmx_u;
    asm("redux.sync.min.u32 %0, %1, 0xffffffff;" : "=r"(wmn_u) : "r"(__float_as_uint(gmn)));
    asm("redux.sync.max.u32 %0, %1, 0xffffffff;" : "=r"(wmx_u) : "r"(__float_as_uint(gmx)));
    if ((tid & 31) == 0) {
        swarp[((tid >> 5) << 1) + 0] = __uint_as_float(wmn_u);
        swarp[((tid >> 5) << 1) + 1] = __uint_as_float(wmx_u);
    }
    __syncthreads();

    // --- cross-warp combine: 4x LDS.128, mins in .x/.z, maxs in .y/.w ---
    const float4 p0 = *reinterpret_cast<const float4*>(&swarp[0]);
    const float4 p1 = *reinterpret_cast<const float4*>(&swarp[4]);
    const float4 p2 = *reinterpret_cast<const float4*>(&swarp[8]);
    const float4 p3 = *reinterpret_cast<const float4*>(&swarp[12]);
    gmn = fminf(fminf(fminf(p0.x, p0.z), fminf(p1.x, p1.z)),
                fminf(fminf(p2.x, p2.z), fminf(p3.x, p3.z)));
    gmx = fmaxf(fmaxf(fmaxf(p0.y, p0.w), fmaxf(p1.y, p1.w)),
                fmaxf(fmaxf(p2.y, p2.w), fmaxf(p3.y, p3.w)));

    const float mul = 255.0f / fmaxf(gmx - gmn, 1.0f);
    const float nb  = -gmn * mul;

    // --- normalize + floor (+scale); float4 stores ---
    float* __restrict__ op = out + (size_t)img * 4096 + (r0 << 6) + c0;
    if (isc == 1.0f) {
#pragma unroll
        for (int i = 0; i < 4; i++) {
            float4 o4;
            o4.x = floorf(fmaf(g[i * 4 + 0], mul, nb));
            o4.y = floorf(fmaf(g[i * 4 + 1], mul, nb));
            o4.z = floorf(fmaf(g[i * 4 + 2], mul, nb));
            o4.w = floorf(fmaf(g[i * 4 + 3], mul, nb));
            *reinterpret_cast<float4*>(op + (i << 6)) = o4;
        }
    } else {
#pragma unroll
        for (int i = 0; i < 4; i++) {
            float4 o4;
            o4.x = floorf(fmaf(g[i * 4 + 0], mul, nb)) * isc;
            o4.y = floorf(fmaf(g[i * 4 + 1], mul, nb)) * isc;
            o4.z = floorf(fmaf(g[i * 4 + 2], mul, nb)) * isc;
            o4.w = floorf(fmaf(g[i * 4 + 3], mul, nb)) * isc;
            *reinterpret_cast<float4*>(op + (i << 6)) = o4;
        }
    }
}

extern "C" void kernel_launch(void* const* d_in, const int* in_sizes, int n_in,
                              void* d_out, int out_size) {
    const float* in      = (const float*)d_in[0];  // (2048,1,64,64) fp32
    const float* w       = (const float*)d_in[1];  // (1,9) fp32
    const float* wf      = (const float*)d_in[2];  // (1,) fp32
    const float* scale_p = (const float*)d_in[3];  // (1,1) fp32
    float* out = (float*)d_out;                    // (1,2048,1,64,64) fp32
    (void)in_sizes; (void)n_in; (void)out_size;

    coeff_kernel<<<1, 1>>>(w, wf, scale_p);
    sobel_norm_kernel<<<NUM_IMG, 256>>>(in, out);
}